// round 4
// baseline (speedup 1.0000x reference)
#include <cuda_runtime.h>

// Shapes (fixed by the problem)
#define BB 64
#define NN 21
#define HH 128
#define WW 128
// Total elements = 64*21*128*128 = 22,020,096 ; /4 = 5,505,024 float4

static constexpr int GRID    = 592;   // 148 SMs * 4
static constexpr int THREADS = 512;
static constexpr int NKP = BB * NN;   // 1344 keypoints

__device__ float g_mse_part[GRID];
__device__ float g_pck_part[GRID];
__device__ unsigned int g_done_ctr;   // zero-init at load; reset by last block

__device__ __forceinline__ float warp_sum(float v) {
    #pragma unroll
    for (int off = 16; off > 0; off >>= 1)
        v += __shfl_down_sync(0xFFFFFFFFu, v, off);
    return v;
}

__device__ __forceinline__ float sqdiff4(float4 a, float4 b, float acc) {
    float d;
    d = a.x - b.x; acc = fmaf(d, d, acc);
    d = a.y - b.y; acc = fmaf(d, d, acc);
    d = a.z - b.z; acc = fmaf(d, d, acc);
    d = a.w - b.w; acc = fmaf(d, d, acc);
    return acc;
}

__global__ void __launch_bounds__(THREADS) fused_loss_kernel(
    const float4* __restrict__ pred4,
    const float4* __restrict__ gt4,
    const float*  __restrict__ pred,   // scalar view for gathers
    const float*  __restrict__ kp,     // (B, N, 2) -> [x, y]
    float* __restrict__ out,
    int n4)
{
    const int tid = threadIdx.x;
    const int tid_global = blockIdx.x * THREADS + tid;

    // ---- keypoint gather (overlapped with streaming; first NKP threads) ----
    float pck_acc = 0.0f;
    if (tid_global < NKP) {
        float xf = __ldg(&kp[2 * tid_global + 0]);
        float yf = __ldg(&kp[2 * tid_global + 1]);
        int x = (int)fminf(fmaxf(xf, 0.0f), (float)(WW - 1));
        int y = (int)fminf(fmaxf(yf, 0.0f), (float)(HH - 1));
        float v = __ldg(&pred[(tid_global * HH + y) * WW + x]);
        float e = 1.0f - v;
        pck_acc = e * e;
    }

    // ---- streaming MSE over a CONTIGUOUS per-block chunk ----
    // Each block owns [start, end); block footprint per unrolled iteration
    // is 512 threads * 16B * 4 = 32KB contiguous per array.
    const int chunk = (n4 + GRID - 1) / GRID;        // 9300
    const int start = blockIdx.x * chunk;
    const int end   = min(start + chunk, n4);

    float acc0 = 0.0f, acc1 = 0.0f, acc2 = 0.0f, acc3 = 0.0f;
    int i = start + tid;
    for (; i + 3 * THREADS < end; i += 4 * THREADS) {
        float4 a0 = __ldcs(&pred4[i]);
        float4 a1 = __ldcs(&pred4[i + THREADS]);
        float4 a2 = __ldcs(&pred4[i + 2 * THREADS]);
        float4 a3 = __ldcs(&pred4[i + 3 * THREADS]);
        float4 b0 = __ldcs(&gt4[i]);
        float4 b1 = __ldcs(&gt4[i + THREADS]);
        float4 b2 = __ldcs(&gt4[i + 2 * THREADS]);
        float4 b3 = __ldcs(&gt4[i + 3 * THREADS]);
        acc0 = sqdiff4(a0, b0, acc0);
        acc1 = sqdiff4(a1, b1, acc1);
        acc2 = sqdiff4(a2, b2, acc2);
        acc3 = sqdiff4(a3, b3, acc3);
    }
    for (; i < end; i += THREADS) {
        float4 a = __ldcs(&pred4[i]);
        float4 b = __ldcs(&gt4[i]);
        acc0 = sqdiff4(a, b, acc0);
    }
    float mse_acc = (acc0 + acc1) + (acc2 + acc3);

    // ---- block reduction of both accumulators ----
    __shared__ float s1[THREADS / 32];
    __shared__ float s2[THREADS / 32];
    int lane = tid & 31;
    int wid  = tid >> 5;
    float m = warp_sum(mse_acc);
    float p = warp_sum(pck_acc);
    if (lane == 0) { s1[wid] = m; s2[wid] = p; }
    __syncthreads();

    __shared__ bool s_is_last;
    if (wid == 0) {
        float mm = (lane < THREADS / 32) ? s1[lane] : 0.0f;
        float pp = (lane < THREADS / 32) ? s2[lane] : 0.0f;
        mm = warp_sum(mm);
        pp = warp_sum(pp);
        if (lane == 0) {
            g_mse_part[blockIdx.x] = mm;
            g_pck_part[blockIdx.x] = pp;
            __threadfence();
            unsigned int prev = atomicAdd(&g_done_ctr, 1u);
            s_is_last = (prev == (unsigned int)(gridDim.x - 1));
        }
    }
    __syncthreads();

    // ---- last block finalizes ----
    if (s_is_last) {
        float ma = 0.0f, pa = 0.0f;
        for (int j = tid; j < GRID; j += THREADS) {
            ma += g_mse_part[j];
            pa += g_pck_part[j];
        }
        float mw = warp_sum(ma);
        float pw = warp_sum(pa);
        if (lane == 0) { s1[wid] = mw; s2[wid] = pw; }
        __syncthreads();
        if (wid == 0) {
            float mm = (lane < THREADS / 32) ? s1[lane] : 0.0f;
            float pp = (lane < THREADS / 32) ? s2[lane] : 0.0f;
            mm = warp_sum(mm);
            pp = warp_sum(pp);
            if (lane == 0) {
                float mse = mm / (float)((long long)BB * NN * HH * WW);
                float pck = pp / (float)NKP;
                out[0] = mse + pck;   // total (weights are 1.0)
                out[1] = mse;
                out[2] = pck;
                g_done_ctr = 0;       // reset for next graph replay
            }
        }
    }
}

extern "C" void kernel_launch(void* const* d_in, const int* in_sizes, int n_in,
                              void* d_out, int out_size)
{
    const float* pred = (const float*)d_in[0];
    const float* gt   = (const float*)d_in[1];
    const float* kp   = (const float*)d_in[2];
    float* out = (float*)d_out;

    int n4 = (BB * NN * HH * WW) / 4;   // 5,505,024

    fused_loss_kernel<<<GRID, THREADS>>>(
        (const float4*)pred, (const float4*)gt, pred, kp, out, n4);
}

// round 5
// speedup vs baseline: 1.0082x; 1.0082x over previous
#include <cuda_runtime.h>

// Shapes (fixed by the problem)
#define BB 64
#define NN 21
#define HH 128
#define WW 128
// Total elements = 64*21*128*128 = 22,020,096 ; /8 = 2,752,512 v8 chunks

static constexpr int GRID    = 1184;  // 148 SMs * 8
static constexpr int THREADS = 256;
static constexpr int NKP = BB * NN;   // 1344 keypoints

__device__ float g_mse_part[GRID];
__device__ float g_pck_part[GRID];
__device__ unsigned int g_done_ctr;   // zero-init at load; reset by last block

__device__ __forceinline__ float warp_sum(float v) {
    #pragma unroll
    for (int off = 16; off > 0; off >>= 1)
        v += __shfl_down_sync(0xFFFFFFFFu, v, off);
    return v;
}

// 256-bit global load (Blackwell sm_100+): 8 floats in one LDG.E.256
__device__ __forceinline__ void ldg256(const float* p,
                                       float& v0, float& v1, float& v2, float& v3,
                                       float& v4, float& v5, float& v6, float& v7) {
    asm volatile("ld.global.nc.v8.f32 {%0,%1,%2,%3,%4,%5,%6,%7}, [%8];"
                 : "=f"(v0), "=f"(v1), "=f"(v2), "=f"(v3),
                   "=f"(v4), "=f"(v5), "=f"(v6), "=f"(v7)
                 : "l"(p));
}

__global__ void __launch_bounds__(THREADS) fused_loss_kernel(
    const float* __restrict__ pred,
    const float* __restrict__ gt,
    const float* __restrict__ kp,     // (B, N, 2) -> [x, y]
    float* __restrict__ out,
    int n8)                            // count of 8-float chunks
{
    const int tid_global = blockIdx.x * THREADS + threadIdx.x;
    const int stride = GRID * THREADS;            // in v8 units

    // ---- keypoint gather (overlapped with streaming; first NKP threads) ----
    float pck_acc = 0.0f;
    if (tid_global < NKP) {
        float xf = __ldg(&kp[2 * tid_global + 0]);
        float yf = __ldg(&kp[2 * tid_global + 1]);
        int x = (int)fminf(fmaxf(xf, 0.0f), (float)(WW - 1));
        int y = (int)fminf(fmaxf(yf, 0.0f), (float)(HH - 1));
        float v = __ldg(&pred[(tid_global * HH + y) * WW + x]);
        float e = 1.0f - v;
        pck_acc = e * e;
    }

    // ---- streaming MSE: 256-bit loads, 2-deep unroll, 2 accumulators ----
    float acc0 = 0.0f, acc1 = 0.0f;
    long long i = tid_global;
    for (; i + stride < n8; i += 2LL * stride) {
        float a0,a1,a2,a3,a4,a5,a6,a7;
        float b0,b1,b2,b3,b4,b5,b6,b7;
        float c0,c1,c2,c3,c4,c5,c6,c7;
        float e0,e1,e2,e3,e4,e5,e6,e7;
        ldg256(pred + i * 8,            a0,a1,a2,a3,a4,a5,a6,a7);
        ldg256(pred + (i + stride) * 8, c0,c1,c2,c3,c4,c5,c6,c7);
        ldg256(gt   + i * 8,            b0,b1,b2,b3,b4,b5,b6,b7);
        ldg256(gt   + (i + stride) * 8, e0,e1,e2,e3,e4,e5,e6,e7);
        float d;
        d = a0-b0; acc0 = fmaf(d,d,acc0);
        d = a1-b1; acc0 = fmaf(d,d,acc0);
        d = a2-b2; acc0 = fmaf(d,d,acc0);
        d = a3-b3; acc0 = fmaf(d,d,acc0);
        d = a4-b4; acc0 = fmaf(d,d,acc0);
        d = a5-b5; acc0 = fmaf(d,d,acc0);
        d = a6-b6; acc0 = fmaf(d,d,acc0);
        d = a7-b7; acc0 = fmaf(d,d,acc0);
        d = c0-e0; acc1 = fmaf(d,d,acc1);
        d = c1-e1; acc1 = fmaf(d,d,acc1);
        d = c2-e2; acc1 = fmaf(d,d,acc1);
        d = c3-e3; acc1 = fmaf(d,d,acc1);
        d = c4-e4; acc1 = fmaf(d,d,acc1);
        d = c5-e5; acc1 = fmaf(d,d,acc1);
        d = c6-e6; acc1 = fmaf(d,d,acc1);
        d = c7-e7; acc1 = fmaf(d,d,acc1);
    }
    for (; i < n8; i += stride) {
        float a0,a1,a2,a3,a4,a5,a6,a7;
        float b0,b1,b2,b3,b4,b5,b6,b7;
        ldg256(pred + i * 8, a0,a1,a2,a3,a4,a5,a6,a7);
        ldg256(gt   + i * 8, b0,b1,b2,b3,b4,b5,b6,b7);
        float d;
        d = a0-b0; acc0 = fmaf(d,d,acc0);
        d = a1-b1; acc0 = fmaf(d,d,acc0);
        d = a2-b2; acc0 = fmaf(d,d,acc0);
        d = a3-b3; acc0 = fmaf(d,d,acc0);
        d = a4-b4; acc0 = fmaf(d,d,acc0);
        d = a5-b5; acc0 = fmaf(d,d,acc0);
        d = a6-b6; acc0 = fmaf(d,d,acc0);
        d = a7-b7; acc0 = fmaf(d,d,acc0);
    }
    float mse_acc = acc0 + acc1;

    // ---- block reduction of both accumulators ----
    __shared__ float s1[THREADS / 32];
    __shared__ float s2[THREADS / 32];
    int lane = threadIdx.x & 31;
    int wid  = threadIdx.x >> 5;
    float m = warp_sum(mse_acc);
    float p = warp_sum(pck_acc);
    if (lane == 0) { s1[wid] = m; s2[wid] = p; }
    __syncthreads();

    __shared__ bool s_is_last;
    if (wid == 0) {
        float mm = (lane < THREADS / 32) ? s1[lane] : 0.0f;
        float pp = (lane < THREADS / 32) ? s2[lane] : 0.0f;
        mm = warp_sum(mm);
        pp = warp_sum(pp);
        if (lane == 0) {
            g_mse_part[blockIdx.x] = mm;
            g_pck_part[blockIdx.x] = pp;
            __threadfence();
            unsigned int prev = atomicAdd(&g_done_ctr, 1u);
            s_is_last = (prev == (unsigned int)(gridDim.x - 1));
        }
    }
    __syncthreads();

    // ---- last block finalizes ----
    if (s_is_last) {
        float ma = 0.0f, pa = 0.0f;
        for (int j = threadIdx.x; j < GRID; j += THREADS) {
            ma += g_mse_part[j];
            pa += g_pck_part[j];
        }
        float mw = warp_sum(ma);
        float pw = warp_sum(pa);
        if (lane == 0) { s1[wid] = mw; s2[wid] = pw; }
        __syncthreads();
        if (wid == 0) {
            float mm = (lane < THREADS / 32) ? s1[lane] : 0.0f;
            float pp = (lane < THREADS / 32) ? s2[lane] : 0.0f;
            mm = warp_sum(mm);
            pp = warp_sum(pp);
            if (lane == 0) {
                float mse = mm / (float)((long long)BB * NN * HH * WW);
                float pck = pp / (float)NKP;
                out[0] = mse + pck;   // total (weights are 1.0)
                out[1] = mse;
                out[2] = pck;
                g_done_ctr = 0;       // reset for next graph replay
            }
        }
    }
}

extern "C" void kernel_launch(void* const* d_in, const int* in_sizes, int n_in,
                              void* d_out, int out_size)
{
    const float* pred = (const float*)d_in[0];
    const float* gt   = (const float*)d_in[1];
    const float* kp   = (const float*)d_in[2];
    float* out = (float*)d_out;

    int n8 = (BB * NN * HH * WW) / 8;   // 2,752,512

    fused_loss_kernel<<<GRID, THREADS>>>(pred, gt, kp, out, n8);
}

// round 6
// speedup vs baseline: 1.0985x; 1.0896x over previous
#include <cuda_runtime.h>

// Shapes (fixed by the problem)
#define BB 64
#define NN 21
#define HH 128
#define WW 128
// Total elements = 64*21*128*128 = 22,020,096 ; /4 = 5,505,024 float4

static constexpr int GRID    = 592;   // 148 SMs * 4 (one full wave at 4 CTAs/SM)
static constexpr int THREADS = 256;
static constexpr int NKP = BB * NN;   // 1344 keypoints

__device__ float2 g_part[GRID];       // (mse, pck) partials
__device__ unsigned int g_done_ctr;   // zero-init at load; reset by last block

__device__ __forceinline__ float warp_sum(float v) {
    #pragma unroll
    for (int off = 16; off > 0; off >>= 1)
        v += __shfl_down_sync(0xFFFFFFFFu, v, off);
    return v;
}

__device__ __forceinline__ float sqdiff4(float4 a, float4 b, float acc) {
    float d;
    d = a.x - b.x; acc = fmaf(d, d, acc);
    d = a.y - b.y; acc = fmaf(d, d, acc);
    d = a.z - b.z; acc = fmaf(d, d, acc);
    d = a.w - b.w; acc = fmaf(d, d, acc);
    return acc;
}

// min 4 blocks/SM -> 64-register budget per thread: lets ptxas keep all
// 8 LDG.128 of one unrolled iteration in flight simultaneously.
__global__ void __launch_bounds__(THREADS, 4) fused_loss_kernel(
    const float4* __restrict__ pred4,
    const float4* __restrict__ gt4,
    const float*  __restrict__ pred,   // scalar view for gathers
    const float*  __restrict__ kp,     // (B, N, 2) -> [x, y]
    float* __restrict__ out,
    int n4)
{
    const int tid_global = blockIdx.x * THREADS + threadIdx.x;
    const int stride = GRID * THREADS;   // 151,552

    // ---- streaming MSE: 4-deep unroll, 4 independent accumulators ----
    float acc0 = 0.0f, acc1 = 0.0f, acc2 = 0.0f, acc3 = 0.0f;
    int i = tid_global;
    #pragma unroll 1
    for (; i + 3 * stride < n4; i += 4 * stride) {
        // 8 independent 128-bit loads — keep ALL in flight (64-reg budget)
        float4 a0 = pred4[i];
        float4 a1 = pred4[i + stride];
        float4 a2 = pred4[i + 2 * stride];
        float4 a3 = pred4[i + 3 * stride];
        float4 b0 = gt4[i];
        float4 b1 = gt4[i + stride];
        float4 b2 = gt4[i + 2 * stride];
        float4 b3 = gt4[i + 3 * stride];
        acc0 = sqdiff4(a0, b0, acc0);
        acc1 = sqdiff4(a1, b1, acc1);
        acc2 = sqdiff4(a2, b2, acc2);
        acc3 = sqdiff4(a3, b3, acc3);
    }
    #pragma unroll 1
    for (; i < n4; i += stride) {
        float4 a = pred4[i];
        float4 b = gt4[i];
        acc0 = sqdiff4(a, b, acc0);
    }
    float mse_acc = (acc0 + acc1) + (acc2 + acc3);

    // ---- keypoint gather (after stream issue; first NKP threads) ----
    float pck_acc = 0.0f;
    if (tid_global < NKP) {
        float2 xy = *(const float2*)&kp[2 * tid_global];
        int x = (int)fminf(fmaxf(xy.x, 0.0f), (float)(WW - 1));
        int y = (int)fminf(fmaxf(xy.y, 0.0f), (float)(HH - 1));
        float v = pred[(tid_global * HH + y) * WW + x];
        float e = 1.0f - v;
        pck_acc = e * e;
    }

    // ---- block reduction of both accumulators ----
    __shared__ float s1[THREADS / 32];
    __shared__ float s2[THREADS / 32];
    int lane = threadIdx.x & 31;
    int wid  = threadIdx.x >> 5;
    float m = warp_sum(mse_acc);
    float p = warp_sum(pck_acc);
    if (lane == 0) { s1[wid] = m; s2[wid] = p; }
    __syncthreads();

    __shared__ bool s_is_last;
    if (wid == 0) {
        float mm = (lane < THREADS / 32) ? s1[lane] : 0.0f;
        float pp = (lane < THREADS / 32) ? s2[lane] : 0.0f;
        mm = warp_sum(mm);
        pp = warp_sum(pp);
        if (lane == 0) {
            g_part[blockIdx.x] = make_float2(mm, pp);
            __threadfence();
            unsigned int prev = atomicAdd(&g_done_ctr, 1u);
            s_is_last = (prev == (unsigned int)(gridDim.x - 1));
        }
    }
    __syncthreads();

    // ---- last block finalizes ----
    if (s_is_last) {
        float ma = 0.0f, pa = 0.0f;
        for (int j = threadIdx.x; j < GRID; j += THREADS) {
            float2 v = g_part[j];
            ma += v.x;
            pa += v.y;
        }
        float mw = warp_sum(ma);
        float pw = warp_sum(pa);
        if (lane == 0) { s1[wid] = mw; s2[wid] = pw; }
        __syncthreads();
        if (wid == 0) {
            float mm = (lane < THREADS / 32) ? s1[lane] : 0.0f;
            float pp = (lane < THREADS / 32) ? s2[lane] : 0.0f;
            mm = warp_sum(mm);
            pp = warp_sum(pp);
            if (lane == 0) {
                float mse = mm / (float)((long long)BB * NN * HH * WW);
                float pck = pp / (float)NKP;
                out[0] = mse + pck;   // total (weights are 1.0)
                out[1] = mse;
                out[2] = pck;
                g_done_ctr = 0;       // reset for next graph replay
            }
        }
    }
}

extern "C" void kernel_launch(void* const* d_in, const int* in_sizes, int n_in,
                              void* d_out, int out_size)
{
    const float* pred = (const float*)d_in[0];
    const float* gt   = (const float*)d_in[1];
    const float* kp   = (const float*)d_in[2];
    float* out = (float*)d_out;

    int n4 = (BB * NN * HH * WW) / 4;   // 5,505,024

    fused_loss_kernel<<<GRID, THREADS>>>(
        (const float4*)pred, (const float4*)gt, pred, kp, out, n4);
}